// round 3
// baseline (speedup 1.0000x reference)
#include <cuda_runtime.h>
#include <cuda_bf16.h>

// Problem dims (fixed by the reference)
constexpr int TOKENS = 8192;
constexpr int INF    = 4096;   // in_features
constexpr int RANK   = 1024;
constexpr int OUTF   = 4096;   // out_features

// Scratch: y / y_q buffer (quantized in place), 32 MB static device global.
__device__ float g_y[(size_t)TOKENS * RANK];
__device__ int   g_amax_bits;

__global__ void k_reset() { g_amax_bits = 0; }

// ---------------------------------------------------------------------------
// GEMM1 (high accuracy): y[M,N] = A[M,K] @ B[N,K]^T, fp32 with chunked-Kahan
// accumulation. BM=128, BN=64, BK=16, 256 threads, 8x4 per-thread microtile.
// Within a BK chunk: plain fmaf into a fresh register (partial sums small ->
// tiny rounding error). Chunk sums merged into (acc, comp) via Kahan using
// __fadd_rn/__fsub_rn intrinsics (immune to fast-math reassociation).
// Net accumulation error ~1e-7 absolute on |y|~1 (vs ~1.6e-6 serial).
// Fused |y| amax reduction into g_amax_bits.
// ---------------------------------------------------------------------------
__global__ __launch_bounds__(256, 2)
void gemm1_kahan(const float* __restrict__ A, const float* __restrict__ B,
                 float* __restrict__ C, int M, int N, int K)
{
    constexpr int BM = 128, BN = 64, BK = 16;
    __shared__ float As[BK][BM];   // [k][m]
    __shared__ float Bs[BK][BN];   // [k][n]

    const int tid = threadIdx.x;
    const int tx  = tid & 15;      // n-dim, 16 threads * 4 cols = 64
    const int ty  = tid >> 4;      // m-dim, 16 threads * 8 rows = 128
    const int m0  = blockIdx.y * BM;
    const int n0  = blockIdx.x * BN;

    float acc[8][4], comp[8][4];
#pragma unroll
    for (int i = 0; i < 8; i++)
#pragma unroll
        for (int j = 0; j < 4; j++) { acc[i][j] = 0.f; comp[i][j] = 0.f; }

    const int numK = K / BK;
    for (int kt = 0; kt < numK; kt++) {
        const int k0 = kt * BK;

        // Load A tile: 128x16 = 512 float4, 2 per thread, coalesced along K.
#pragma unroll
        for (int it = 0; it < 2; it++) {
            int i   = tid + it * 256;
            int mm  = i >> 2;
            int kk4 = (i & 3) * 4;
            float4 v = *reinterpret_cast<const float4*>(
                A + (size_t)(m0 + mm) * K + k0 + kk4);
            As[kk4 + 0][mm] = v.x; As[kk4 + 1][mm] = v.y;
            As[kk4 + 2][mm] = v.z; As[kk4 + 3][mm] = v.w;
        }
        // Load B tile: 64x16 = 256 float4, 1 per thread.
        {
            int i   = tid;
            int nn  = i >> 2;
            int kk4 = (i & 3) * 4;
            float4 v = *reinterpret_cast<const float4*>(
                B + (size_t)(n0 + nn) * K + k0 + kk4);
            Bs[kk4 + 0][nn] = v.x; Bs[kk4 + 1][nn] = v.y;
            Bs[kk4 + 2][nn] = v.z; Bs[kk4 + 3][nn] = v.w;
        }
        __syncthreads();

        // Chunk accumulation (fresh registers, exact-ish for small partials).
        float chunk[8][4];
#pragma unroll
        for (int i = 0; i < 8; i++)
#pragma unroll
            for (int j = 0; j < 4; j++) chunk[i][j] = 0.f;

#pragma unroll
        for (int kk = 0; kk < BK; kk++) {
            float a[8], b[4];
            *reinterpret_cast<float4*>(&a[0]) =
                *reinterpret_cast<const float4*>(&As[kk][ty * 8]);
            *reinterpret_cast<float4*>(&a[4]) =
                *reinterpret_cast<const float4*>(&As[kk][ty * 8 + 4]);
            *reinterpret_cast<float4*>(&b[0]) =
                *reinterpret_cast<const float4*>(&Bs[kk][tx * 4]);
#pragma unroll
            for (int i = 0; i < 8; i++)
#pragma unroll
                for (int j = 0; j < 4; j++)
                    chunk[i][j] = fmaf(a[i], b[j], chunk[i][j]);
        }

        // Kahan merge: acc += chunk with compensation (explicit IEEE intrinsics).
#pragma unroll
        for (int i = 0; i < 8; i++)
#pragma unroll
            for (int j = 0; j < 4; j++) {
                float yk = __fsub_rn(chunk[i][j], comp[i][j]);
                float t  = __fadd_rn(acc[i][j], yk);
                comp[i][j] = __fsub_rn(__fsub_rn(t, acc[i][j]), yk);
                acc[i][j]  = t;
            }
        __syncthreads();
    }

    // Epilogue: fold compensation, store, fused amax.
    float lmax = 0.f;
#pragma unroll
    for (int i = 0; i < 8; i++) {
        const int m = m0 + ty * 8 + i;
        const int n = n0 + tx * 4;
        float4 v;
        v.x = __fsub_rn(acc[i][0], comp[i][0]);
        v.y = __fsub_rn(acc[i][1], comp[i][1]);
        v.z = __fsub_rn(acc[i][2], comp[i][2]);
        v.w = __fsub_rn(acc[i][3], comp[i][3]);
        *reinterpret_cast<float4*>(C + (size_t)m * N + n) = v;
        lmax = fmaxf(lmax, fmaxf(fmaxf(fabsf(v.x), fabsf(v.y)),
                                 fmaxf(fabsf(v.z), fabsf(v.w))));
    }
#pragma unroll
    for (int o = 16; o > 0; o >>= 1)
        lmax = fmaxf(lmax, __shfl_xor_sync(0xffffffffu, lmax, o));
    if ((tid & 31) == 0)
        atomicMax(&g_amax_bits, __float_as_int(lmax));   // lmax >= 0: int cmp OK

}

// ---------------------------------------------------------------------------
// GEMM2 (plain fp32): out[M,N] = A[M,K] @ B[N,K]^T + bias[n].
// BM=BN=128, BK=16, 256 threads, 8x8 microtile. Accumulation error ~8e-7
// relative -- harmless (no decision boundary downstream).
// ---------------------------------------------------------------------------
__global__ __launch_bounds__(256, 2)
void gemm2_bias(const float* __restrict__ A, const float* __restrict__ B,
                const float* __restrict__ bias, float* __restrict__ C,
                int M, int N, int K)
{
    constexpr int BM = 128, BN = 128, BK = 16;
    __shared__ float As[BK][BM];
    __shared__ float Bs[BK][BN];

    const int tid = threadIdx.x;
    const int tx  = tid & 15;
    const int ty  = tid >> 4;
    const int m0  = blockIdx.y * BM;
    const int n0  = blockIdx.x * BN;

    float acc[8][8];
#pragma unroll
    for (int i = 0; i < 8; i++)
#pragma unroll
        for (int j = 0; j < 8; j++) acc[i][j] = 0.f;

    const int numK = K / BK;
    for (int kt = 0; kt < numK; kt++) {
        const int k0 = kt * BK;
#pragma unroll
        for (int it = 0; it < 2; it++) {
            int i   = tid + it * 256;
            int mm  = i >> 2;
            int kk4 = (i & 3) * 4;
            float4 v = *reinterpret_cast<const float4*>(
                A + (size_t)(m0 + mm) * K + k0 + kk4);
            As[kk4 + 0][mm] = v.x; As[kk4 + 1][mm] = v.y;
            As[kk4 + 2][mm] = v.z; As[kk4 + 3][mm] = v.w;
        }
#pragma unroll
        for (int it = 0; it < 2; it++) {
            int i   = tid + it * 256;
            int nn  = i >> 2;
            int kk4 = (i & 3) * 4;
            float4 v = *reinterpret_cast<const float4*>(
                B + (size_t)(n0 + nn) * K + k0 + kk4);
            Bs[kk4 + 0][nn] = v.x; Bs[kk4 + 1][nn] = v.y;
            Bs[kk4 + 2][nn] = v.z; Bs[kk4 + 3][nn] = v.w;
        }
        __syncthreads();

#pragma unroll
        for (int kk = 0; kk < BK; kk++) {
            float a[8], b[8];
            *reinterpret_cast<float4*>(&a[0]) =
                *reinterpret_cast<const float4*>(&As[kk][ty * 8]);
            *reinterpret_cast<float4*>(&a[4]) =
                *reinterpret_cast<const float4*>(&As[kk][ty * 8 + 4]);
            *reinterpret_cast<float4*>(&b[0]) =
                *reinterpret_cast<const float4*>(&Bs[kk][tx * 8]);
            *reinterpret_cast<float4*>(&b[4]) =
                *reinterpret_cast<const float4*>(&Bs[kk][tx * 8 + 4]);
#pragma unroll
            for (int i = 0; i < 8; i++)
#pragma unroll
                for (int j = 0; j < 8; j++)
                    acc[i][j] = fmaf(a[i], b[j], acc[i][j]);
        }
        __syncthreads();
    }

#pragma unroll
    for (int i = 0; i < 8; i++) {
        const int m = m0 + ty * 8 + i;
#pragma unroll
        for (int j = 0; j < 8; j += 4) {
            const int n = n0 + tx * 8 + j;
            float4 v = make_float4(acc[i][j], acc[i][j + 1],
                                   acc[i][j + 2], acc[i][j + 3]);
            v.x = __fadd_rn(v.x, __ldg(bias + n));
            v.y = __fadd_rn(v.y, __ldg(bias + n + 1));
            v.z = __fadd_rn(v.z, __ldg(bias + n + 2));
            v.w = __fadd_rn(v.w, __ldg(bias + n + 3));
            *reinterpret_cast<float4*>(C + (size_t)m * N + n) = v;
        }
    }
}

// ---------------------------------------------------------------------------
// Fake-quant pass (in place): y_q = clip(round(y/scale), -4, 3) * scale.
// IEEE division + rintf (round-half-to-even) to match jnp exactly; all via
// _rn intrinsics so fast-math cannot alter semantics.
// ---------------------------------------------------------------------------
__device__ __forceinline__ float fq1(float x, float scale) {
    float q = rintf(__fdiv_rn(x, scale));
    q = fminf(fmaxf(q, -4.f), 3.f);
    return __fmul_rn(q, scale);
}

__global__ void k_quant(float* __restrict__ y, int n4) {
    const float amax  = __int_as_float(g_amax_bits);
    const float scale = __fdiv_rn(fmaxf(amax, 1e-8f), 3.0f);
    int i = blockIdx.x * blockDim.x + threadIdx.x;
    if (i < n4) {
        float4 v = reinterpret_cast<float4*>(y)[i];
        v.x = fq1(v.x, scale); v.y = fq1(v.y, scale);
        v.z = fq1(v.z, scale); v.w = fq1(v.w, scale);
        reinterpret_cast<float4*>(y)[i] = v;
    }
}

// ---------------------------------------------------------------------------
extern "C" void kernel_launch(void* const* d_in, const int* in_sizes, int n_in,
                              void* d_out, int out_size)
{
    const float* input = (const float*)d_in[0];   // [TOKENS, INF]
    const float* B_w   = (const float*)d_in[1];   // [RANK, INF]
    const float* A_w   = (const float*)d_in[2];   // [OUTF, RANK]
    const float* A_b   = (const float*)d_in[3];   // [OUTF]
    float*       out   = (float*)d_out;           // [TOKENS, OUTF]

    float* y = nullptr;
    cudaGetSymbolAddress((void**)&y, g_y);        // no alloc; capture-safe

    // 1) reset amax
    k_reset<<<1, 1>>>();

    // 2) y = input @ B_w^T  (chunked-Kahan fp32, fused amax)
    {
        dim3 grid(RANK / 64, TOKENS / 128);
        gemm1_kahan<<<grid, 256>>>(input, B_w, y, TOKENS, RANK, INF);
    }

    // 3) fake-quant in place
    {
        const int n4 = TOKENS * RANK / 4;
        k_quant<<<(n4 + 255) / 256, 256>>>(y, n4);
    }

    // 4) out = y_q @ A_w^T + A_b  (plain fp32, fused bias)
    {
        dim3 grid(OUTF / 128, TOKENS / 128);
        gemm2_bias<<<grid, 256>>>(y, A_w, A_b, out, TOKENS, OUTF, RANK);
    }
}